// round 4
// baseline (speedup 1.0000x reference)
#include <cuda_runtime.h>
#include <cstdint>
#include <math.h>

#define NB   1024
#define NC   119
#define ND   1024
#define NH   16
#define SEQ  64
#define MR   (NB*SEQ)     // 65536 rows
#define KPAD 128
#define PADK 36           // smem row pitch in u32 (32 + 4 pad)
#define BUFU (128 * PADK) // u32 per buffer per operand
#define GSMEM (4 * BUFU * 4)  // 2 bufs x (A,B) in bytes = 73728

// ---------------- scratch ----------------------------------------------------
__device__ float g_xin [(size_t)MR * KPAD];
__device__ float g_Wt  [(size_t)3 * ND * ND];   // transposed tf32 weights (qkv fused / reused)
__device__ float g_bqkv[3 * ND];
__device__ float g_x   [(size_t)MR * ND];
__device__ float g_qkv [(size_t)MR * 3 * ND];
__device__ float g_o   [(size_t)MR * ND];

// ---------------- helpers -----------------------------------------------------
__device__ __forceinline__ uint32_t f2tf32(float f) {
    uint32_t r; asm("cvt.rna.tf32.f32 %0, %1;" : "=r"(r) : "f"(f)); return r;
}
__device__ __forceinline__ uint32_t smem_u32(const void* p) {
    uint32_t a;
    asm("{ .reg .u64 t; cvta.to.shared.u64 t, %1; cvt.u32.u64 %0, t; }" : "=r"(a) : "l"(p));
    return a;
}
__device__ __forceinline__ void cp_async16(uint32_t saddr, const void* gptr) {
    asm volatile("cp.async.ca.shared.global [%0], [%1], 16;" :: "r"(saddr), "l"(gptr));
}
#define CP_COMMIT() asm volatile("cp.async.commit_group;")
#define CP_WAIT(n)  asm volatile("cp.async.wait_group %0;" :: "n"(n))

__device__ __forceinline__ void mma_tf32(float* d, const uint32_t* a, const uint32_t* b) {
    asm volatile("mma.sync.aligned.m16n8k8.row.col.f32.tf32.tf32.f32 "
        "{%0,%1,%2,%3}, {%4,%5,%6,%7}, {%8,%9}, {%0,%1,%2,%3};"
        : "+f"(d[0]), "+f"(d[1]), "+f"(d[2]), "+f"(d[3])
        : "r"(a[0]), "r"(a[1]), "r"(a[2]), "r"(a[3]), "r"(b[0]), "r"(b[1]));
}

// ---------------- board (B,C,8,8) -> xin (B*64, KPAD) ------------------------
__global__ void board_transpose_kernel(const float* __restrict__ board) {
    __shared__ float tile[NC * 65];
    int b = blockIdx.x;
    const float* src = board + (size_t)b * NC * SEQ;
    for (int i = threadIdx.x; i < NC * SEQ; i += blockDim.x) {
        int c = i >> 6, s = i & 63;
        tile[c * 65 + s] = src[i];
    }
    __syncthreads();
    float* dst = g_xin + (size_t)b * SEQ * KPAD;
    for (int i = threadIdx.x; i < SEQ * KPAD; i += blockDim.x) {
        int s = i >> 7, c = i & 127;
        dst[i] = (c < NC) ? tile[c * 65 + s] : 0.f;
    }
}

// ------------- weight transpose + tf32 round: W(R x Cw) -> Wt(Cw x Rpad) -----
__global__ void transpose_kernel(const float* __restrict__ W, float* __restrict__ Wt,
                                 int R, int Cw, int Rpad) {
    __shared__ float t[32][33];
    int bx = blockIdx.x * 32;
    int by = blockIdx.y * 32;
    int tx = threadIdx.x, ty = threadIdx.y;
    #pragma unroll
    for (int i = 0; i < 4; i++) {
        int r = by + ty + i * 8, c = bx + tx;
        t[ty + i * 8][tx] = (r < R) ? W[(size_t)r * Cw + c] : 0.f;
    }
    __syncthreads();
    #pragma unroll
    for (int i = 0; i < 4; i++) {
        int c = bx + ty + i * 8, r = by + tx;
        Wt[(size_t)c * Rpad + r] = __uint_as_float(f2tf32(t[tx][ty + i * 8]));
    }
}

__global__ void concat_bias_kernel(const float* __restrict__ bq,
                                   const float* __restrict__ bk,
                                   const float* __restrict__ bv) {
    int i = blockIdx.x * blockDim.x + threadIdx.x;
    if (i >= 3 * ND) return;
    g_bqkv[i] = (i < ND) ? bq[i] : (i < 2 * ND) ? bk[i - ND] : bv[i - 2 * ND];
}

// ---------------- tf32 mma.sync GEMM (cp.async pipelined, BK=32) ---------------
// C(M x N) = A(M x K, fp32) @ Bt(N x K, tf32 bits)^T + bias (+res) (+pos)
// CTA 128x128, 8 warps 2(m)x4(n), warp tile 64x32 via m16n8k8.
__global__ __launch_bounds__(256, 2)
void gemm_mma_kernel(const float* __restrict__ A, const float* __restrict__ Bt,
                     const float* __restrict__ bias,
                     const float* __restrict__ res, const float* __restrict__ pos,
                     float* __restrict__ C, int K, int ldc)
{
    extern __shared__ uint32_t dynsm[];
    uint32_t* As = dynsm;            // [2][BUFU]
    uint32_t* Bs = dynsm + 2 * BUFU; // [2][BUFU]

    const int tid = threadIdx.x;
    const int lane = tid & 31, wid = tid >> 5;
    const int g = lane >> 2, t = lane & 3;
    const int wm = wid >> 2, wn = wid & 3;
    const int bm = blockIdx.y * 128, bn = blockIdx.x * 128;

    // loader: each thread owns row (tid>>1), 16-col segment ((tid&1)*16)
    const int lrow = tid >> 1, lseg = (tid & 1) * 16;
    const float* pA = A  + (size_t)(bm + lrow) * K + lseg;
    const float* pB = Bt + (size_t)(bn + lrow) * K + lseg;
    const uint32_t bsAddr = smem_u32(Bs) + (uint32_t)(lrow * PADK + lseg) * 4;

    float acc[4][4][4];
    #pragma unroll
    for (int i = 0; i < 4; i++)
        #pragma unroll
        for (int j = 0; j < 4; j++)
            #pragma unroll
            for (int r = 0; r < 4; r++) acc[i][j][r] = 0.f;

    const int nk = K / 32;
    float4 ra[4];

    // ---- prologue: stage 0 ----
    #pragma unroll
    for (int q = 0; q < 4; q++) ra[q] = *(const float4*)(pA + q * 4);
    #pragma unroll
    for (int q = 0; q < 4; q++) cp_async16(bsAddr + q * 16, pB + q * 4);
    CP_COMMIT();
    {
        uint32_t* s = &As[lrow * PADK + lseg];
        #pragma unroll
        for (int q = 0; q < 4; q++) {
            s[q*4+0] = f2tf32(ra[q].x); s[q*4+1] = f2tf32(ra[q].y);
            s[q*4+2] = f2tf32(ra[q].z); s[q*4+3] = f2tf32(ra[q].w);
        }
    }
    if (nk > 1) {
        #pragma unroll
        for (int q = 0; q < 4; q++) ra[q] = *(const float4*)(pA + 32 + q * 4);
    }

    for (int it = 0; it < nk; it++) {
        const int cur = it & 1, nxt = cur ^ 1;
        if (it + 1 < nk) {
            #pragma unroll
            for (int q = 0; q < 4; q++)
                cp_async16(bsAddr + nxt * (BUFU * 4) + q * 16, pB + (it + 1) * 32 + q * 4);
            CP_COMMIT();
            uint32_t* s = &As[nxt * BUFU + lrow * PADK + lseg];
            #pragma unroll
            for (int q = 0; q < 4; q++) {
                s[q*4+0] = f2tf32(ra[q].x); s[q*4+1] = f2tf32(ra[q].y);
                s[q*4+2] = f2tf32(ra[q].z); s[q*4+3] = f2tf32(ra[q].w);
            }
        }
        if (it + 2 < nk) {
            #pragma unroll
            for (int q = 0; q < 4; q++) ra[q] = *(const float4*)(pA + (it + 2) * 32 + q * 4);
        }
        if (it + 1 < nk) { CP_WAIT(1); } else { CP_WAIT(0); }
        __syncthreads();

        const uint32_t* Ab = &As[cur * BUFU];
        const uint32_t* Bb = &Bs[cur * BUFU];
        #pragma unroll
        for (int ks = 0; ks < 4; ks++) {
            const int kb = ks * 8;
            uint32_t a[4][4], b[4][2];
            #pragma unroll
            for (int i = 0; i < 4; i++) {
                int r = (wm * 64 + i * 16 + g) * PADK + kb + t;
                a[i][0] = Ab[r];
                a[i][1] = Ab[r + 8 * PADK];
                a[i][2] = Ab[r + 4];
                a[i][3] = Ab[r + 8 * PADK + 4];
            }
            #pragma unroll
            for (int j = 0; j < 4; j++) {
                int c = (wn * 32 + j * 8 + g) * PADK + kb + t;
                b[j][0] = Bb[c];
                b[j][1] = Bb[c + 4];
            }
            #pragma unroll
            for (int i = 0; i < 4; i++)
                #pragma unroll
                for (int j = 0; j < 4; j++)
                    mma_tf32(acc[i][j], a[i], b[j]);
        }
        __syncthreads();
    }

    // epilogue
    #pragma unroll
    for (int i = 0; i < 4; i++) {
        int r0 = bm + wm * 64 + i * 16 + g;
        #pragma unroll
        for (int j = 0; j < 4; j++) {
            int cg = bn + wn * 32 + j * 8 + t * 2;
            float2 b2 = *(const float2*)&bias[cg];
            float o00 = acc[i][j][0] + b2.x, o01 = acc[i][j][1] + b2.y;
            float o10 = acc[i][j][2] + b2.x, o11 = acc[i][j][3] + b2.y;
            size_t row0 = (size_t)r0 * ldc + cg;
            size_t row1 = (size_t)(r0 + 8) * ldc + cg;
            if (res) {
                float2 x0 = *(const float2*)&res[row0];
                float2 x1 = *(const float2*)&res[row1];
                o00 += x0.x; o01 += x0.y; o10 += x1.x; o11 += x1.y;
            }
            if (pos) {
                float2 p0 = *(const float2*)&pos[(size_t)(r0 & 63) * ND + cg];
                float2 p1 = *(const float2*)&pos[(size_t)((r0 + 8) & 63) * ND + cg];
                o00 += p0.x; o01 += p0.y; o10 += p1.x; o11 += p1.y;
            }
            *(float2*)&C[row0] = make_float2(o00, o01);
            *(float2*)&C[row1] = make_float2(o10, o11);
        }
    }
}

// ---------------- attention: one block per (b,h), reads fused qkv -------------
__global__ __launch_bounds__(256)
void attn_kernel(const float* __restrict__ rel_bias)
{
    extern __shared__ float sm[];
    float* qst = sm;
    float* kst = sm + 64 * 68;
    float* vs  = sm + 2 * 64 * 68;
    float* ps  = vs + 64 * 64;

    const int h = blockIdx.x, b = blockIdx.y;
    const int tid = threadIdx.x;
    const size_t base = (size_t)b * SEQ * (3 * ND) + h * 64;

    for (int i = tid; i < 64 * 64; i += 256) {
        int s = i >> 6, d = i & 63;
        size_t gidx = base + (size_t)s * (3 * ND) + d;
        qst[d * 68 + s] = g_qkv[gidx];
        kst[d * 68 + s] = g_qkv[gidx + ND];
        vs [s * 64 + d] = g_qkv[gidx + 2 * ND];
    }
    __syncthreads();

    const int tj = tid & 15, ti = tid >> 4;
    const int i0 = ti * 4, j0 = tj * 4;

    float acc[4][4];
    #pragma unroll
    for (int a = 0; a < 4; a++)
        #pragma unroll
        for (int c = 0; c < 4; c++) acc[a][c] = 0.f;

    #pragma unroll 4
    for (int d = 0; d < 64; d++) {
        float4 qv = *(const float4*)&qst[d * 68 + i0];
        float4 kv = *(const float4*)&kst[d * 68 + j0];
        float qa[4] = {qv.x, qv.y, qv.z, qv.w};
        float kb[4] = {kv.x, kv.y, kv.z, kv.w};
        #pragma unroll
        for (int a = 0; a < 4; a++)
            #pragma unroll
            for (int c = 0; c < 4; c++)
                acc[a][c] = fmaf(qa[a], kb[c], acc[a][c]);
    }

    const float* rb = rel_bias + (size_t)h * 64 * 64;
    #pragma unroll
    for (int a = 0; a < 4; a++) {
        float4 b4 = *(const float4*)&rb[(i0 + a) * 64 + j0];
        acc[a][0] = acc[a][0] * 0.125f + b4.x;
        acc[a][1] = acc[a][1] * 0.125f + b4.y;
        acc[a][2] = acc[a][2] * 0.125f + b4.z;
        acc[a][3] = acc[a][3] * 0.125f + b4.w;
    }

    #pragma unroll
    for (int a = 0; a < 4; a++) {
        float mx = fmaxf(fmaxf(acc[a][0], acc[a][1]), fmaxf(acc[a][2], acc[a][3]));
        #pragma unroll
        for (int off = 1; off < 16; off <<= 1)
            mx = fmaxf(mx, __shfl_xor_sync(0xffffffffu, mx, off));
        float s = 0.f;
        #pragma unroll
        for (int c = 0; c < 4; c++) { acc[a][c] = __expf(acc[a][c] - mx); s += acc[a][c]; }
        #pragma unroll
        for (int off = 1; off < 16; off <<= 1)
            s += __shfl_xor_sync(0xffffffffu, s, off);
        float inv = 1.f / s;
        #pragma unroll
        for (int c = 0; c < 4; c++) acc[a][c] *= inv;
        *(float4*)&ps[(i0 + a) * 64 + j0] =
            make_float4(acc[a][0], acc[a][1], acc[a][2], acc[a][3]);
    }
    __syncthreads();

    float oc[4][4];
    #pragma unroll
    for (int a = 0; a < 4; a++)
        #pragma unroll
        for (int c = 0; c < 4; c++) oc[a][c] = 0.f;

    #pragma unroll 4
    for (int j = 0; j < 64; j++) {
        float4 vv = *(const float4*)&vs[j * 64 + j0];
        float vb[4] = {vv.x, vv.y, vv.z, vv.w};
        float pa[4];
        #pragma unroll
        for (int a = 0; a < 4; a++) pa[a] = ps[(i0 + a) * 64 + j];
        #pragma unroll
        for (int a = 0; a < 4; a++)
            #pragma unroll
            for (int c = 0; c < 4; c++)
                oc[a][c] = fmaf(pa[a], vb[c], oc[a][c]);
    }

    const size_t obase = (size_t)b * SEQ * ND + h * 64;
    #pragma unroll
    for (int a = 0; a < 4; a++)
        *(float4*)&g_o[obase + (size_t)(i0 + a) * ND + j0] =
            make_float4(oc[a][0], oc[a][1], oc[a][2], oc[a][3]);
}

// ---------------- LayerNorm ---------------------------------------------------
__device__ __forceinline__ float block_sum(float v, float* red) {
    #pragma unroll
    for (int o = 16; o > 0; o >>= 1) v += __shfl_xor_sync(0xffffffffu, v, o);
    int w = threadIdx.x >> 5;
    if ((threadIdx.x & 31) == 0) red[w] = v;
    __syncthreads();
    if (threadIdx.x < 8) {
        v = red[threadIdx.x];
        #pragma unroll
        for (int o = 4; o > 0; o >>= 1) v += __shfl_xor_sync(0xffu, v, o);
        if (threadIdx.x == 0) red[0] = v;
    }
    __syncthreads();
    float r = red[0];
    __syncthreads();
    return r;
}

__global__ __launch_bounds__(256)
void ln_kernel(const float* __restrict__ gamma, const float* __restrict__ beta,
               float* __restrict__ out)
{
    __shared__ float red[32];
    const size_t row = (size_t)blockIdx.x * ND;
    const int t4 = threadIdx.x * 4;
    float4 v = *(const float4*)&g_x[row + t4];

    float s = v.x + v.y + v.z + v.w;
    float mu = block_sum(s, red) * (1.f / ND);

    float dx = v.x - mu, dy = v.y - mu, dz = v.z - mu, dw = v.w - mu;
    float sq = dx * dx + dy * dy + dz * dz + dw * dw;
    float var = block_sum(sq, red) * (1.f / ND);
    float inv = rsqrtf(var + 1e-5f);

    float4 g4 = *(const float4*)&gamma[t4];
    float4 b4 = *(const float4*)&beta[t4];
    float4 o4;
    o4.x = dx * inv * g4.x + b4.x;
    o4.y = dy * inv * g4.y + b4.y;
    o4.z = dz * inv * g4.z + b4.z;
    o4.w = dw * inv * g4.w + b4.w;
    *(float4*)&out[row + t4] = o4;
}

// ---------------- launch -------------------------------------------------------
extern "C" void kernel_launch(void* const* d_in, const int* in_sizes, int n_in,
                              void* d_out, int out_size)
{
    const float* board = (const float*)d_in[0];
    const float* embW  = (const float*)d_in[1];
    const float* embB  = (const float*)d_in[2];
    const float* pos   = (const float*)d_in[3];
    const float* Wq    = (const float*)d_in[4];
    const float* bq    = (const float*)d_in[5];
    const float* Wk    = (const float*)d_in[6];
    const float* bk    = (const float*)d_in[7];
    const float* Wv    = (const float*)d_in[8];
    const float* bv    = (const float*)d_in[9];
    const float* Wo    = (const float*)d_in[10];
    const float* bo    = (const float*)d_in[11];
    const float* relb  = (const float*)d_in[12];
    const float* lng   = (const float*)d_in[13];
    const float* lnb   = (const float*)d_in[14];
    float* out = (float*)d_out;

    float *xin, *wt, *bqkv, *x, *qkv, *o;
    cudaGetSymbolAddress((void**)&xin,  g_xin);
    cudaGetSymbolAddress((void**)&wt,   g_Wt);
    cudaGetSymbolAddress((void**)&bqkv, g_bqkv);
    cudaGetSymbolAddress((void**)&x,    g_x);
    cudaGetSymbolAddress((void**)&qkv,  g_qkv);
    cudaGetSymbolAddress((void**)&o,    g_o);

    cudaFuncSetAttribute(gemm_mma_kernel,
                         cudaFuncAttributeMaxDynamicSharedMemorySize, GSMEM);

    board_transpose_kernel<<<NB, 256>>>(board);
    concat_bias_kernel<<<(3 * ND + 255) / 256, 256>>>(bq, bk, bv);

    dim3 tb(32, 8);

    // embed: x = xin @ embW + emb_b + pos   (K = 128 padded)
    transpose_kernel<<<dim3(ND / 32, KPAD / 32), tb>>>(embW, wt, NC, ND, KPAD);
    gemm_mma_kernel<<<dim3(ND / 128, MR / 128), 256, GSMEM>>>(
        xin, wt, embB, nullptr, pos, x, KPAD, ND);

    // fused QKV: qkv = x @ [Wq|Wk|Wv] + [bq|bk|bv]   (N = 3072)
    transpose_kernel<<<dim3(ND / 32, ND / 32), tb>>>(Wq, wt,               ND, ND, ND);
    transpose_kernel<<<dim3(ND / 32, ND / 32), tb>>>(Wk, wt + (size_t)ND*ND,   ND, ND, ND);
    transpose_kernel<<<dim3(ND / 32, ND / 32), tb>>>(Wv, wt + (size_t)2*ND*ND, ND, ND, ND);
    gemm_mma_kernel<<<dim3(3 * ND / 128, MR / 128), 256, GSMEM>>>(
        x, wt, bqkv, nullptr, nullptr, qkv, ND, 3 * ND);

    // attention
    const int attn_smem = (2 * 64 * 68 + 2 * 64 * 64) * (int)sizeof(float);
    cudaFuncSetAttribute(attn_kernel, cudaFuncAttributeMaxDynamicSharedMemorySize, attn_smem);
    attn_kernel<<<dim3(NH, NB), 256, attn_smem>>>(relb);

    // y = x + o @ Wo + bo   (into g_x)
    transpose_kernel<<<dim3(ND / 32, ND / 32), tb>>>(Wo, wt, ND, ND, ND);
    gemm_mma_kernel<<<dim3(ND / 128, MR / 128), 256, GSMEM>>>(
        o, wt, bo, x, nullptr, x, ND, ND);

    ln_kernel<<<MR, 256>>>(lng, lnb, out);
}

// round 5
// speedup vs baseline: 1.0419x; 1.0419x over previous
#include <cuda_runtime.h>
#include <cstdint>
#include <math.h>

#define NB   1024
#define NC   119
#define ND   1024
#define NH   16
#define SEQ  64
#define MR   (NB*SEQ)     // 65536 rows
#define KPAD 128

// GEMM tiling: CTA 256(M) x 128(N), BK=32, 8 warps (4m x 2n), warp tile 64x64
#define PADKA 36
#define PADKB 40
#define ASTG  (256 * PADKA)         // u32 per A stage
#define BSTG  (128 * PADKB)         // u32 per B stage
#define NSTG  3
#define GSMEM ((ASTG + BSTG) * NSTG * 4)   // 172032 bytes

// ---------------- scratch ----------------------------------------------------
__device__ float g_xin [(size_t)MR * KPAD];
__device__ float g_Wt  [(size_t)3 * ND * ND];   // transposed tf32 weights, k-permuted
__device__ float g_bqkv[3 * ND];
__device__ float g_x   [(size_t)MR * ND];
__device__ float g_qkv [(size_t)MR * 3 * ND];
__device__ float g_o   [(size_t)MR * ND];

// ---------------- helpers -----------------------------------------------------
__device__ __forceinline__ uint32_t f2tf32(float f) {
    uint32_t r; asm("cvt.rna.tf32.f32 %0, %1;" : "=r"(r) : "f"(f)); return r;
}
__device__ __forceinline__ float roundtf(float f) { return __uint_as_float(f2tf32(f)); }

__device__ __forceinline__ uint32_t smem_u32(const void* p) {
    uint32_t a;
    asm("{ .reg .u64 t; cvta.to.shared.u64 t, %1; cvt.u32.u64 %0, t; }" : "=r"(a) : "l"(p));
    return a;
}
__device__ __forceinline__ void cp_async16(uint32_t saddr, const void* gptr) {
    asm volatile("cp.async.cg.shared.global [%0], [%1], 16;" :: "r"(saddr), "l"(gptr));
}
#define CP_COMMIT() asm volatile("cp.async.commit_group;")
#define CP_WAIT(n)  asm volatile("cp.async.wait_group %0;" :: "n"(n))

__device__ __forceinline__ void mma_tf32(float* d, const uint32_t* a, const uint32_t* b) {
    asm volatile("mma.sync.aligned.m16n8k8.row.col.f32.tf32.tf32.f32 "
        "{%0,%1,%2,%3}, {%4,%5,%6,%7}, {%8,%9}, {%0,%1,%2,%3};"
        : "+f"(d[0]), "+f"(d[1]), "+f"(d[2]), "+f"(d[3])
        : "r"(a[0]), "r"(a[1]), "r"(a[2]), "r"(a[3]), "r"(b[0]), "r"(b[1]));
}

// ---------------- board (B,C,8,8) -> xin (B*64, KPAD), tf32-rounded ----------
__global__ void board_transpose_kernel(const float* __restrict__ board) {
    __shared__ float tile[NC * 65];
    int b = blockIdx.x;
    const float* src = board + (size_t)b * NC * SEQ;
    for (int i = threadIdx.x; i < NC * SEQ; i += blockDim.x) {
        int c = i >> 6, s = i & 63;
        tile[c * 65 + s] = src[i];
    }
    __syncthreads();
    float* dst = g_xin + (size_t)b * SEQ * KPAD;
    for (int i = threadIdx.x; i < SEQ * KPAD; i += blockDim.x) {
        int s = i >> 7, c = i & 127;
        dst[i] = (c < NC) ? roundtf(tile[c * 65 + s]) : 0.f;
    }
}

// ------- weight transpose + tf32 round + k-permute: W(RxCw) -> Wt(Cw x Rpad) --
// k-permutation within each 8-group: pos(k) = 2*(k&3) + ((k&4)>>2)
__global__ void transpose_kernel(const float* __restrict__ W, float* __restrict__ Wt,
                                 int R, int Cw, int Rpad) {
    __shared__ float t[32][33];
    int bx = blockIdx.x * 32;
    int by = blockIdx.y * 32;
    int tx = threadIdx.x, ty = threadIdx.y;
    #pragma unroll
    for (int i = 0; i < 4; i++) {
        int r = by + ty + i * 8, c = bx + tx;
        t[ty + i * 8][tx] = (r < R) ? W[(size_t)r * Cw + c] : 0.f;
    }
    __syncthreads();
    #pragma unroll
    for (int i = 0; i < 4; i++) {
        int c = bx + ty + i * 8, r = by + tx;
        int rp = (r & ~7) | (((r & 3) << 1) | ((r & 4) >> 2));
        Wt[(size_t)c * Rpad + rp] = roundtf(t[tx][ty + i * 8]);
    }
}

__global__ void concat_bias_kernel(const float* __restrict__ bq,
                                   const float* __restrict__ bk,
                                   const float* __restrict__ bv) {
    int i = blockIdx.x * blockDim.x + threadIdx.x;
    if (i >= 3 * ND) return;
    g_bqkv[i] = (i < ND) ? bq[i] : (i < 2 * ND) ? bk[i - ND] : bv[i - 2 * ND];
}

// ---------------- tf32 mma.sync GEMM, fully cp.async pipelined ----------------
// C(M x N) = A(M x K) @ Bt(N x K)^T + bias (+res) (+pos), optional tf32-rounded out
__global__ __launch_bounds__(256, 1)
void gemm_mma_kernel(const float* __restrict__ A, const float* __restrict__ Bt,
                     const float* __restrict__ bias,
                     const float* __restrict__ res, const float* __restrict__ pos,
                     float* __restrict__ C, int K, int ldc, int round_out)
{
    extern __shared__ uint32_t dynsm[];
    uint32_t* As = dynsm;                 // [NSTG][256][PADKA]
    uint32_t* Bs = dynsm + NSTG * ASTG;   // [NSTG][128][PADKB]

    const int tid = threadIdx.x;
    const int lane = tid & 31, wid = tid >> 5;
    const int g = lane >> 2, t = lane & 3;
    const int wm = wid >> 1, wn = wid & 1;       // 4m x 2n warps
    const int bm = blockIdx.y * 256, bn = blockIdx.x * 128;

    // loader mapping
    const int lrow = tid >> 1;                   // 0..127
    const int lcol = (tid & 1) * 16;             // u32 offset: 0 or 16
    const float* pA0 = A  + (size_t)(bm + lrow) * K + lcol;
    const float* pA1 = A  + (size_t)(bm + lrow + 128) * K + lcol;
    const float* pB  = Bt + (size_t)(bn + lrow) * K + lcol;
    const uint32_t aAddr0 = smem_u32(As) + (uint32_t)(lrow * PADKA + lcol) * 4;
    const uint32_t aAddr1 = smem_u32(As) + (uint32_t)((lrow + 128) * PADKA + lcol) * 4;
    const uint32_t bAddr  = smem_u32(Bs) + (uint32_t)(lrow * PADKB + lcol) * 4;

    const int nk = K / 32;

    float acc[4][8][4];
    #pragma unroll
    for (int i = 0; i < 4; i++)
        #pragma unroll
        for (int j = 0; j < 8; j++)
            #pragma unroll
            for (int r = 0; r < 4; r++) acc[i][j][r] = 0.f;

    // prologue: stages 0 and 1
    #pragma unroll
    for (int st = 0; st < 2; st++) {
        const int k0 = st * 32;
        const uint32_t so = (uint32_t)st;
        #pragma unroll
        for (int q = 0; q < 4; q++) {
            cp_async16(aAddr0 + so * (ASTG * 4) + q * 16, pA0 + k0 + q * 4);
            cp_async16(aAddr1 + so * (ASTG * 4) + q * 16, pA1 + k0 + q * 4);
            cp_async16(bAddr  + so * (BSTG * 4) + q * 16, pB  + k0 + q * 4);
        }
        CP_COMMIT();
    }

    for (int it = 0; it < nk; it++) {
        const int s = it % NSTG;
        if (it + 1 < nk) { CP_WAIT(1); } else { CP_WAIT(0); }
        __syncthreads();

        if (it + 2 < nk) {
            const int s2 = (it + 2) % NSTG;
            const int k0 = (it + 2) * 32;
            #pragma unroll
            for (int q = 0; q < 4; q++) {
                cp_async16(aAddr0 + s2 * (ASTG * 4) + q * 16, pA0 + k0 + q * 4);
                cp_async16(aAddr1 + s2 * (ASTG * 4) + q * 16, pA1 + k0 + q * 4);
                cp_async16(bAddr  + s2 * (BSTG * 4) + q * 16, pB  + k0 + q * 4);
            }
            CP_COMMIT();
        }

        const uint32_t* Ab = As + s * ASTG;
        const uint32_t* Bb = Bs + s * BSTG;
        #pragma unroll
        for (int ks = 0; ks < 4; ks++) {
            const int kb = ks * 8;
            uint32_t a[4][4];
            uint2 b[8];
            #pragma unroll
            for (int i = 0; i < 4; i++) {
                int r = (wm * 64 + i * 16 + g) * PADKA + kb + t;
                a[i][0] = Ab[r];
                a[i][1] = Ab[r + 8 * PADKA];
                a[i][2] = Ab[r + 4];
                a[i][3] = Ab[r + 8 * PADKA + 4];
            }
            #pragma unroll
            for (int j = 0; j < 8; j++) {
                int c = (wn * 64 + j * 8 + g) * PADKB + kb + 2 * t;
                b[j] = *(const uint2*)&Bb[c];
            }
            #pragma unroll
            for (int i = 0; i < 4; i++)
                #pragma unroll
                for (int j = 0; j < 8; j++)
                    mma_tf32(acc[i][j], a[i], (const uint32_t*)&b[j]);
        }
    }

    // epilogue
    #pragma unroll
    for (int i = 0; i < 4; i++) {
        int r0 = bm + wm * 64 + i * 16 + g;
        #pragma unroll
        for (int j = 0; j < 8; j++) {
            int cg = bn + wn * 64 + j * 8 + t * 2;
            float2 b2 = *(const float2*)&bias[cg];
            float o00 = acc[i][j][0] + b2.x, o01 = acc[i][j][1] + b2.y;
            float o10 = acc[i][j][2] + b2.x, o11 = acc[i][j][3] + b2.y;
            size_t row0 = (size_t)r0 * ldc + cg;
            size_t row1 = (size_t)(r0 + 8) * ldc + cg;
            if (res) {
                float2 x0 = *(const float2*)&res[row0];
                float2 x1 = *(const float2*)&res[row1];
                o00 += x0.x; o01 += x0.y; o10 += x1.x; o11 += x1.y;
            }
            if (pos) {
                float2 p0 = *(const float2*)&pos[(size_t)(r0 & 63) * ND + cg];
                float2 p1 = *(const float2*)&pos[(size_t)((r0 + 8) & 63) * ND + cg];
                o00 += p0.x; o01 += p0.y; o10 += p1.x; o11 += p1.y;
            }
            if (round_out) {
                o00 = roundtf(o00); o01 = roundtf(o01);
                o10 = roundtf(o10); o11 = roundtf(o11);
            }
            *(float2*)&C[row0] = make_float2(o00, o01);
            *(float2*)&C[row1] = make_float2(o10, o11);
        }
    }
}

// ---------------- attention: one block per (b,h), reads fused qkv -------------
__global__ __launch_bounds__(256)
void attn_kernel(const float* __restrict__ rel_bias)
{
    extern __shared__ float sm[];
    float* qst = sm;
    float* kst = sm + 64 * 68;
    float* vs  = sm + 2 * 64 * 68;
    float* ps  = vs + 64 * 64;

    const int h = blockIdx.x, b = blockIdx.y;
    const int tid = threadIdx.x;
    const size_t base = (size_t)b * SEQ * (3 * ND) + h * 64;

    for (int i = tid; i < 64 * 64; i += 256) {
        int s = i >> 6, d = i & 63;
        size_t gidx = base + (size_t)s * (3 * ND) + d;
        qst[d * 68 + s] = g_qkv[gidx];
        kst[d * 68 + s] = g_qkv[gidx + ND];
        vs [s * 64 + d] = g_qkv[gidx + 2 * ND];
    }
    __syncthreads();

    const int tj = tid & 15, ti = tid >> 4;
    const int i0 = ti * 4, j0 = tj * 4;

    float acc[4][4];
    #pragma unroll
    for (int a = 0; a < 4; a++)
        #pragma unroll
        for (int c = 0; c < 4; c++) acc[a][c] = 0.f;

    #pragma unroll 4
    for (int d = 0; d < 64; d++) {
        float4 qv = *(const float4*)&qst[d * 68 + i0];
        float4 kv = *(const float4*)&kst[d * 68 + j0];
        float qa[4] = {qv.x, qv.y, qv.z, qv.w};
        float kb[4] = {kv.x, kv.y, kv.z, kv.w};
        #pragma unroll
        for (int a = 0; a < 4; a++)
            #pragma unroll
            for (int c = 0; c < 4; c++)
                acc[a][c] = fmaf(qa[a], kb[c], acc[a][c]);
    }

    const float* rb = rel_bias + (size_t)h * 64 * 64;
    #pragma unroll
    for (int a = 0; a < 4; a++) {
        float4 b4 = *(const float4*)&rb[(i0 + a) * 64 + j0];
        acc[a][0] = acc[a][0] * 0.125f + b4.x;
        acc[a][1] = acc[a][1] * 0.125f + b4.y;
        acc[a][2] = acc[a][2] * 0.125f + b4.z;
        acc[a][3] = acc[a][3] * 0.125f + b4.w;
    }

    #pragma unroll
    for (int a = 0; a < 4; a++) {
        float mx = fmaxf(fmaxf(acc[a][0], acc[a][1]), fmaxf(acc[a][2], acc[a][3]));
        #pragma unroll
        for (int off = 1; off < 16; off <<= 1)
            mx = fmaxf(mx, __shfl_xor_sync(0xffffffffu, mx, off));
        float s = 0.f;
        #pragma unroll
        for (int c = 0; c < 4; c++) { acc[a][c] = __expf(acc[a][c] - mx); s += acc[a][c]; }
        #pragma unroll
        for (int off = 1; off < 16; off <<= 1)
            s += __shfl_xor_sync(0xffffffffu, s, off);
        float inv = 1.f / s;
        #pragma unroll
        for (int c = 0; c < 4; c++) acc[a][c] *= inv;
        *(float4*)&ps[(i0 + a) * 64 + j0] =
            make_float4(acc[a][0], acc[a][1], acc[a][2], acc[a][3]);
    }
    __syncthreads();

    float oc[4][4];
    #pragma unroll
    for (int a = 0; a < 4; a++)
        #pragma unroll
        for (int c = 0; c < 4; c++) oc[a][c] = 0.f;

    #pragma unroll 4
    for (int j = 0; j < 64; j++) {
        float4 vv = *(const float4*)&vs[j * 64 + j0];
        float vb[4] = {vv.x, vv.y, vv.z, vv.w};
        float pa[4];
        #pragma unroll
        for (int a = 0; a < 4; a++) pa[a] = ps[(i0 + a) * 64 + j];
        #pragma unroll
        for (int a = 0; a < 4; a++)
            #pragma unroll
            for (int c = 0; c < 4; c++)
                oc[a][c] = fmaf(pa[a], vb[c], oc[a][c]);
    }

    const size_t obase = (size_t)b * SEQ * ND + h * 64;
    #pragma unroll
    for (int a = 0; a < 4; a++)
        *(float4*)&g_o[obase + (size_t)(i0 + a) * ND + j0] =
            make_float4(roundtf(oc[a][0]), roundtf(oc[a][1]),
                        roundtf(oc[a][2]), roundtf(oc[a][3]));
}

// ---------------- LayerNorm ---------------------------------------------------
__device__ __forceinline__ float block_sum(float v, float* red) {
    #pragma unroll
    for (int o = 16; o > 0; o >>= 1) v += __shfl_xor_sync(0xffffffffu, v, o);
    int w = threadIdx.x >> 5;
    if ((threadIdx.x & 31) == 0) red[w] = v;
    __syncthreads();
    if (threadIdx.x < 8) {
        v = red[threadIdx.x];
        #pragma unroll
        for (int o = 4; o > 0; o >>= 1) v += __shfl_xor_sync(0xffu, v, o);
        if (threadIdx.x == 0) red[0] = v;
    }
    __syncthreads();
    float r = red[0];
    __syncthreads();
    return r;
}

__global__ __launch_bounds__(256)
void ln_kernel(const float* __restrict__ gamma, const float* __restrict__ beta,
               float* __restrict__ out)
{
    __shared__ float red[32];
    const size_t row = (size_t)blockIdx.x * ND;
    const int t4 = threadIdx.x * 4;
    float4 v = *(const float4*)&g_x[row + t4];

    float s = v.x + v.y + v.z + v.w;
    float mu = block_sum(s, red) * (1.f / ND);

    float dx = v.x - mu, dy = v.y - mu, dz = v.z - mu, dw = v.w - mu;
    float sq = dx * dx + dy * dy + dz * dz + dw * dw;
    float var = block_sum(sq, red) * (1.f / ND);
    float inv = rsqrtf(var + 1e-5f);

    float4 g4 = *(const float4*)&gamma[t4];
    float4 b4 = *(const float4*)&beta[t4];
    float4 o4;
    o4.x = dx * inv * g4.x + b4.x;
    o4.y = dy * inv * g4.y + b4.y;
    o4.z = dz * inv * g4.z + b4.z;
    o4.w = dw * inv * g4.w + b4.w;
    *(float4*)&out[row + t4] = o4;
}

// ---------------- launch -------------------------------------------------------
extern "C" void kernel_launch(void* const* d_in, const int* in_sizes, int n_in,
                              void* d_out, int out_size)
{
    const float* board = (const float*)d_in[0];
    const float* embW  = (const float*)d_in[1];
    const float* embB  = (const float*)d_in[2];
    const float* pos   = (const float*)d_in[3];
    const float* Wq    = (const float*)d_in[4];
    const float* bq    = (const float*)d_in[5];
    const float* Wk    = (const float*)d_in[6];
    const float* bk    = (const float*)d_in[7];
    const float* Wv    = (const float*)d_in[8];
    const float* bv    = (const float*)d_in[9];
    const float* Wo    = (const float*)d_in[10];
    const float* bo    = (const float*)d_in[11];
    const float* relb  = (const float*)d_in[12];
    const float* lng   = (const float*)d_in[13];
    const float* lnb   = (const float*)d_in[14];
    float* out = (float*)d_out;

    float *xin, *wt, *bqkv, *x, *qkv, *o;
    cudaGetSymbolAddress((void**)&xin,  g_xin);
    cudaGetSymbolAddress((void**)&wt,   g_Wt);
    cudaGetSymbolAddress((void**)&bqkv, g_bqkv);
    cudaGetSymbolAddress((void**)&x,    g_x);
    cudaGetSymbolAddress((void**)&qkv,  g_qkv);
    cudaGetSymbolAddress((void**)&o,    g_o);

    cudaFuncSetAttribute(gemm_mma_kernel,
                         cudaFuncAttributeMaxDynamicSharedMemorySize, GSMEM);

    board_transpose_kernel<<<NB, 256>>>(board);
    concat_bias_kernel<<<(3 * ND + 255) / 256, 256>>>(bq, bk, bv);

    dim3 tb(32, 8);

    // embed: x = tf32( xin @ embW + emb_b + pos )   (K = 128 padded)
    transpose_kernel<<<dim3(ND / 32, KPAD / 32), tb>>>(embW, wt, NC, ND, KPAD);
    gemm_mma_kernel<<<dim3(ND / 128, MR / 256), 256, GSMEM>>>(
        xin, wt, embB, nullptr, pos, x, KPAD, ND, 1);

    // fused QKV: qkv = x @ [Wq|Wk|Wv] + [bq|bk|bv]   (N = 3072)
    transpose_kernel<<<dim3(ND / 32, ND / 32), tb>>>(Wq, wt,                 ND, ND, ND);
    transpose_kernel<<<dim3(ND / 32, ND / 32), tb>>>(Wk, wt + (size_t)ND*ND,   ND, ND, ND);
    transpose_kernel<<<dim3(ND / 32, ND / 32), tb>>>(Wv, wt + (size_t)2*ND*ND, ND, ND, ND);
    gemm_mma_kernel<<<dim3(3 * ND / 128, MR / 256), 256, GSMEM>>>(
        x, wt, bqkv, nullptr, nullptr, qkv, ND, 3 * ND, 0);

    // attention (writes tf32-rounded o)
    const int attn_smem = (2 * 64 * 68 + 2 * 64 * 64) * (int)sizeof(float);
    cudaFuncSetAttribute(attn_kernel, cudaFuncAttributeMaxDynamicSharedMemorySize, attn_smem);
    attn_kernel<<<dim3(NH, NB), 256, attn_smem>>>(relb);

    // y = x + o @ Wo + bo   (into g_x, full fp32 for LN)
    transpose_kernel<<<dim3(ND / 32, ND / 32), tb>>>(Wo, wt, ND, ND, ND);
    gemm_mma_kernel<<<dim3(ND / 128, MR / 256), 256, GSMEM>>>(
        o, wt, bo, x, nullptr, x, ND, ND, 0);

    ln_kernel<<<MR, 256>>>(lng, lnb, out);
}